// round 1
// baseline (speedup 1.0000x reference)
#include <cuda_runtime.h>
#include <math.h>

#define BATCH 2
#define NTOK 256
#define NATOM 2048
#define ROWS 8
#define NTHREADS 256

// ---------------- device scratch (no allocations allowed) ----------------
__device__ double g_acc[BATCH][5];     // bond_num, bond_den, ce, csum, msum
__device__ double g_mom[BATCH][17];    // W, Mask, Swx[3], Swg[3], Sxg[9]
__device__ double g_mse[BATCH];
__device__ float  g_Rot[BATCH][15];    // R[9], mu_g[3], mu_x[3]
__device__ int    g_tok[BATCH][NATOM];
__device__ float  g_isnuc[BATCH][NATOM];
__device__ float  g_watom[BATCH][NATOM];
__device__ float  g_aL[BATCH][NATOM];  // is_ligand * tm at atom's token
__device__ float  g_bL[BATCH][NATOM];  // is_poly   * tm at atom's token

// ---------------- zero atomic accumulators (graph replay safe) -----------
__global__ void zero_kernel() {
    int i = threadIdx.x;
    if (i < BATCH * 5) ((double*)g_acc)[i] = 0.0;
}

// ---------------- per-token -> per-atom preparation -----------------------
__global__ void prep_kernel(const float* __restrict__ isp, const float* __restrict__ isd,
                            const float* __restrict__ isr, const float* __restrict__ isl,
                            const float* __restrict__ tmask, const int* __restrict__ npt) {
    int b = blockIdx.x;
    int tid = threadIdx.x;

    __shared__ int   cum[NTOK];
    __shared__ float s_nuc[NTOK], s_w[NTOK], s_a[NTOK], s_b[NTOK];

    float tm = tmask[b * NTOK + tid];
    float dv = isd[b * NTOK + tid];
    float rv = isr[b * NTOK + tid];
    float lv = isl[b * NTOK + tid];
    float pv = isp[b * NTOK + tid];

    s_nuc[tid] = (dv + rv) * tm;
    s_w[tid]   = (1.0f + 5.0f * dv + 5.0f * rv + 10.0f * lv) * tm;
    s_a[tid]   = lv * tm;
    s_b[tid]   = (pv + dv + rv) * tm;
    cum[tid]   = npt[b * NTOK + tid];
    __syncthreads();

    // inclusive scan (Hillis-Steele)
    for (int off = 1; off < NTOK; off <<= 1) {
        int v = (tid >= off) ? cum[tid - off] : 0;
        __syncthreads();
        cum[tid] += v;
        __syncthreads();
    }
    int total = cum[NTOK - 1];

    for (int k = 0; k < NATOM / NTOK; k++) {
        int l = k * NTOK + tid;
        if (l < total) {
            // first j with cum[j] > l
            int lo = 0, hi = NTOK - 1;
            while (lo < hi) {
                int mid = (lo + hi) >> 1;
                if (cum[mid] > l) hi = mid; else lo = mid + 1;
            }
            g_tok[b][l]   = lo;
            g_isnuc[b][l] = s_nuc[lo];
            g_watom[b][l] = s_w[lo];
            g_aL[b][l]    = s_a[lo];
            g_bL[b][l]    = s_b[lo];
        } else {
            g_tok[b][l] = 0;
            g_isnuc[b][l] = 0.0f; g_watom[b][l] = 0.0f;
            g_aL[b][l] = 0.0f;    g_bL[b][l] = 0.0f;
        }
    }
}

// ---------------- main pairwise kernel: bond loss + smooth LDDT ----------
__global__ void pair_kernel(const float* __restrict__ x, const float* __restrict__ gt,
                            const float* __restrict__ gmask, const float* __restrict__ tb) {
    int b    = blockIdx.y;
    int row0 = blockIdx.x * ROWS;
    int tid  = threadIdx.x;

    __shared__ float rx[ROWS][3], rg[ROWS][3];
    __shared__ float rm[ROWS], rnuc[ROWS], raL[ROWS];
    __shared__ int   rtok[ROWS];

    const float* xb  = x  + (size_t)b * NATOM * 3;
    const float* gb  = gt + (size_t)b * NATOM * 3;
    const float* mb  = gmask + (size_t)b * NATOM;
    const float* tbb = tb + (size_t)b * NTOK * NTOK;

    if (tid < ROWS) {
        int l = row0 + tid;
        rx[tid][0] = xb[3*l+0]; rx[tid][1] = xb[3*l+1]; rx[tid][2] = xb[3*l+2];
        rg[tid][0] = gb[3*l+0]; rg[tid][1] = gb[3*l+1]; rg[tid][2] = gb[3*l+2];
        rm[tid]   = mb[l];
        rnuc[tid] = g_isnuc[b][l];
        raL[tid]  = g_aL[b][l];
        rtok[tid] = g_tok[b][l];
    }
    __syncthreads();

    const float C05 = 0.60653066f;   // e^-0.5
    const float C1  = 0.36787944f;   // e^-1
    const float C2  = 0.13533528f;   // e^-2
    const float C4  = 0.018315639f;  // e^-4

    float a0 = 0.f, a1 = 0.f, a2 = 0.f, a3 = 0.f, a4 = 0.f;

    for (int ci = 0; ci < NATOM / NTHREADS; ci++) {
        int m = ci * NTHREADS + tid;
        float cx0 = xb[3*m+0], cx1 = xb[3*m+1], cx2 = xb[3*m+2];
        float cg0 = gb[3*m+0], cg1 = gb[3*m+1], cg2 = gb[3*m+2];
        float cm  = mb[m];
        float cbL = g_bL[b][m];
        int   ctk = g_tok[b][m];

        #pragma unroll
        for (int r = 0; r < ROWS; r++) {
            float d0 = rx[r][0] - cx0, d1 = rx[r][1] - cx1, d2c = rx[r][2] - cx2;
            float dd = fmaf(d0, d0, fmaf(d1, d1, d2c * d2c));
            float dxv = sqrtf(dd + 1e-12f);

            float e0 = rg[r][0] - cg0, e1 = rg[r][1] - cg1, e2 = rg[r][2] - cg2;
            float gg = fmaf(e0, e0, fmaf(e1, e1, e2 * e2));
            float dgv = sqrtf(gg + 1e-12f);

            float pm   = rm[r] * cm;
            float wb   = raL[r] * cbL * __ldg(&tbb[rtok[r] * NTOK + ctk]) * pm;
            float diff = dxv - dgv;
            a0 = fmaf(diff * diff, wb, a0);
            a1 += wb;

            float d  = fabsf(diff);
            float E  = __expf(d);
            float e  = 0.25f * (__fdividef(1.f, fmaf(E, C05, 1.f))
                              + __fdividef(1.f, fmaf(E, C1,  1.f))
                              + __fdividef(1.f, fmaf(E, C2,  1.f))
                              + __fdividef(1.f, fmaf(E, C4,  1.f)));

            float lt30 = (dgv < 30.f) ? 1.f : 0.f;
            float lt15 = (dgv < 15.f) ? 1.f : 0.f;
            float c    = fmaf(rnuc[r], lt30 - lt15, lt15);
            float m2   = ((row0 + r) != m) ? pm : 0.f;

            a2 = fmaf(c * e, m2, a2);
            a3 = fmaf(c, m2, a3);
            a4 += m2;
        }
    }

    // block reduction -> atomicAdd double
    __shared__ float red[8][5];
    int lane = tid & 31, w = tid >> 5;
    float vals[5] = {a0, a1, a2, a3, a4};
    #pragma unroll
    for (int k = 0; k < 5; k++) {
        float v = vals[k];
        for (int off = 16; off > 0; off >>= 1) v += __shfl_xor_sync(0xffffffffu, v, off);
        if (lane == 0) red[w][k] = v;
    }
    __syncthreads();
    if (tid < 5) {
        float s = 0.f;
        #pragma unroll
        for (int ww = 0; ww < 8; ww++) s += red[ww][tid];
        atomicAdd(&g_acc[b][tid], (double)s);
    }
}

// ---------------- weighted moment sums for Kabsch -------------------------
__global__ void moments_kernel(const float* __restrict__ x, const float* __restrict__ gt,
                               const float* __restrict__ gmask) {
    int b = blockIdx.x, tid = threadIdx.x;
    const float* xb = x  + (size_t)b * NATOM * 3;
    const float* gb = gt + (size_t)b * NATOM * 3;
    const float* mb = gmask + (size_t)b * NATOM;

    double s[17];
    #pragma unroll
    for (int q = 0; q < 17; q++) s[q] = 0.0;

    for (int k = 0; k < NATOM / NTHREADS; k++) {
        int l = k * NTHREADS + tid;
        float mk = mb[l];
        float wm = g_watom[b][l] * mk;
        float x0 = xb[3*l+0], x1 = xb[3*l+1], x2 = xb[3*l+2];
        float g0 = gb[3*l+0], g1 = gb[3*l+1], g2 = gb[3*l+2];
        s[0] += wm; s[1] += mk;
        s[2] += (double)(wm*x0); s[3] += (double)(wm*x1); s[4] += (double)(wm*x2);
        s[5] += (double)(wm*g0); s[6] += (double)(wm*g1); s[7] += (double)(wm*g2);
        s[8]  += (double)(wm*x0*g0); s[9]  += (double)(wm*x0*g1); s[10] += (double)(wm*x0*g2);
        s[11] += (double)(wm*x1*g0); s[12] += (double)(wm*x1*g1); s[13] += (double)(wm*x1*g2);
        s[14] += (double)(wm*x2*g0); s[15] += (double)(wm*x2*g1); s[16] += (double)(wm*x2*g2);
    }

    __shared__ double sh[NTHREADS];
    for (int q = 0; q < 17; q++) {
        sh[tid] = s[q];
        __syncthreads();
        for (int off = NTHREADS / 2; off > 0; off >>= 1) {
            if (tid < off) sh[tid] += sh[tid + off];
            __syncthreads();
        }
        if (tid == 0) g_mom[b][q] = sh[0];
        __syncthreads();
    }
}

// ---------------- Horn quaternion Kabsch (1 thread / batch) --------------
__global__ void kabsch_kernel() {
    int b = threadIdx.x;
    if (b >= BATCH) return;

    double W = g_mom[b][0];
    double invW = 1.0 / W;
    double sx[3] = {g_mom[b][2], g_mom[b][3], g_mom[b][4]};
    double sg[3] = {g_mom[b][5], g_mom[b][6], g_mom[b][7]};
    double H[3][3];
    for (int i = 0; i < 3; i++)
        for (int j = 0; j < 3; j++)
            H[i][j] = g_mom[b][8 + i * 3 + j] - sx[i] * sg[j] * invW;
    double mux[3] = {sx[0]*invW, sx[1]*invW, sx[2]*invW};
    double mug[3] = {sg[0]*invW, sg[1]*invW, sg[2]*invW};

    // Horn: left = gt (source), right = x (target). S_ij = sum gt_i x_j = H[j][i]
    double Sxx = H[0][0], Sxy = H[1][0], Sxz = H[2][0];
    double Syx = H[0][1], Syy = H[1][1], Syz = H[2][1];
    double Szx = H[0][2], Szy = H[1][2], Szz = H[2][2];

    double N[4][4] = {
        { Sxx+Syy+Szz,  Syz-Szy,       Szx-Sxz,       Sxy-Syx      },
        { Syz-Szy,      Sxx-Syy-Szz,   Sxy+Syx,       Szx+Sxz      },
        { Szx-Sxz,      Sxy+Syx,      -Sxx+Syy-Szz,   Syz+Szy      },
        { Sxy-Syx,      Szx+Sxz,       Syz+Szy,      -Sxx-Syy+Szz  }};

    double fro = 0.0;
    for (int i = 0; i < 4; i++) for (int j = 0; j < 4; j++) fro += N[i][j]*N[i][j];
    double shift = sqrt(fro) + 1.0;

    double q[4] = {1.0, 1e-4, 2e-4, 3e-4};
    for (int it = 0; it < 256; it++) {
        double p[4];
        for (int i = 0; i < 4; i++) {
            double v = shift * q[i];
            for (int j = 0; j < 4; j++) v += N[i][j] * q[j];
            p[i] = v;
        }
        double nn = 1.0 / sqrt(p[0]*p[0] + p[1]*p[1] + p[2]*p[2] + p[3]*p[3]);
        for (int i = 0; i < 4; i++) q[i] = p[i] * nn;
    }
    double qw = q[0], qx = q[1], qy = q[2], qz = q[3];
    double R[3][3] = {
        {1.0-2.0*(qy*qy+qz*qz), 2.0*(qx*qy-qw*qz),     2.0*(qx*qz+qw*qy)},
        {2.0*(qx*qy+qw*qz),     1.0-2.0*(qx*qx+qz*qz), 2.0*(qy*qz-qw*qx)},
        {2.0*(qx*qz-qw*qy),     2.0*(qy*qz+qw*qx),     1.0-2.0*(qx*qx+qy*qy)}};

    // orientation self-check: maximize <R, H>
    double f1 = 0.0, f2 = 0.0;
    for (int i = 0; i < 3; i++)
        for (int j = 0; j < 3; j++) { f1 += R[i][j]*H[i][j]; f2 += R[j][i]*H[i][j]; }
    if (f2 > f1) {
        for (int i = 0; i < 3; i++)
            for (int j = i + 1; j < 3; j++) { double tmp = R[i][j]; R[i][j] = R[j][i]; R[j][i] = tmp; }
    }

    for (int i = 0; i < 3; i++)
        for (int j = 0; j < 3; j++) g_Rot[b][i*3+j] = (float)R[i][j];
    for (int i = 0; i < 3; i++) { g_Rot[b][9+i] = (float)mug[i]; g_Rot[b][12+i] = (float)mux[i]; }
}

// ---------------- weighted MSE against aligned gt -------------------------
__global__ void mse_kernel(const float* __restrict__ x, const float* __restrict__ gt,
                           const float* __restrict__ gmask) {
    int b = blockIdx.x, tid = threadIdx.x;
    const float* xb = x  + (size_t)b * NATOM * 3;
    const float* gb = gt + (size_t)b * NATOM * 3;
    const float* mb = gmask + (size_t)b * NATOM;

    float R00 = g_Rot[b][0], R01 = g_Rot[b][1], R02 = g_Rot[b][2];
    float R10 = g_Rot[b][3], R11 = g_Rot[b][4], R12 = g_Rot[b][5];
    float R20 = g_Rot[b][6], R21 = g_Rot[b][7], R22 = g_Rot[b][8];
    float mg0 = g_Rot[b][9],  mg1 = g_Rot[b][10], mg2 = g_Rot[b][11];
    float mx0 = g_Rot[b][12], mx1 = g_Rot[b][13], mx2 = g_Rot[b][14];

    double s = 0.0;
    for (int k = 0; k < NATOM / NTHREADS; k++) {
        int l = k * NTHREADS + tid;
        float g0 = gb[3*l+0] - mg0, g1 = gb[3*l+1] - mg1, g2 = gb[3*l+2] - mg2;
        float a0 = R00*g0 + R01*g1 + R02*g2 + mx0;
        float a1 = R10*g0 + R11*g1 + R12*g2 + mx1;
        float a2 = R20*g0 + R21*g1 + R22*g2 + mx2;
        float d0 = xb[3*l+0] - a0, d1 = xb[3*l+1] - a1, d2 = xb[3*l+2] - a2;
        float e = d0*d0 + d1*d1 + d2*d2;
        s += (double)(e * g_watom[b][l] * mb[l]);
    }

    __shared__ double sh[NTHREADS];
    sh[tid] = s;
    __syncthreads();
    for (int off = NTHREADS / 2; off > 0; off >>= 1) {
        if (tid < off) sh[tid] += sh[tid + off];
        __syncthreads();
    }
    if (tid == 0) g_mse[b] = sh[0];
}

// ---------------- combine -------------------------------------------------
__global__ void final_kernel(const float* __restrict__ t, float* __restrict__ out) {
    double loss = 0.0;
    for (int b = 0; b < BATCH; b++) {
        double lbond = g_acc[b][0] / g_acc[b][1];
        double ce_m  = g_acc[b][2] / g_acc[b][4];
        double c_m   = g_acc[b][3] / g_acc[b][4];
        double llddt = 1.0 - ce_m / c_m;
        double lmse  = (g_mse[b] / g_mom[b][1]) * (1.0 / 3.0);
        double tv = (double)t[b];
        double wt = (tv * tv + 256.0) / ((tv + 16.0) * (tv + 16.0));
        loss += wt * (lmse + lbond) + llddt;
    }
    out[0] = (float)(loss / BATCH);
}

// ---------------- launch ---------------------------------------------------
extern "C" void kernel_launch(void* const* d_in, const int* in_sizes, int n_in,
                              void* d_out, int out_size) {
    const float* x   = (const float*)d_in[0];
    const float* gt  = (const float*)d_in[1];
    const float* gm  = (const float*)d_in[2];
    const float* isp = (const float*)d_in[3];
    const float* isd = (const float*)d_in[4];
    const float* isr = (const float*)d_in[5];
    const float* isl = (const float*)d_in[6];
    const float* tb  = (const float*)d_in[7];
    const float* tm  = (const float*)d_in[8];
    const int*   npt = (const int*)d_in[9];
    const float* t   = (const float*)d_in[10];
    float* out = (float*)d_out;

    zero_kernel<<<1, 64>>>();
    prep_kernel<<<BATCH, NTOK>>>(isp, isd, isr, isl, tm, npt);
    pair_kernel<<<dim3(NATOM / ROWS, BATCH), NTHREADS>>>(x, gt, gm, tb);
    moments_kernel<<<BATCH, NTHREADS>>>(x, gt, gm);
    kabsch_kernel<<<1, 32>>>();
    mse_kernel<<<BATCH, NTHREADS>>>(x, gt, gm);
    final_kernel<<<1, 1>>>(t, out);
}

// round 2
// speedup vs baseline: 9.6815x; 9.6815x over previous
#include <cuda_runtime.h>
#include <math.h>

#define BATCH 2
#define NTOK 256
#define NATOM 2048
#define ROWS 8
#define NTHREADS 256

// ---------------- device scratch (no allocations allowed) ----------------
__device__ double g_acc[BATCH][5];     // bond_num, bond_den, ce, csum, msum
__device__ double g_mom[BATCH][17];    // W, Mask, Swx[3], Swg[3], Sxg[9]
__device__ double g_mse[BATCH];
__device__ float  g_Rot[BATCH][15];    // R[9], mu_g[3], mu_x[3]
__device__ int    g_tok[BATCH][NATOM];
__device__ float  g_isnuc[BATCH][NATOM];
__device__ float  g_watom[BATCH][NATOM];
__device__ float  g_aL[BATCH][NATOM];  // is_ligand * tm at atom's token
__device__ float  g_bL[BATCH][NATOM];  // is_poly   * tm at atom's token

// ---------------- per-token -> per-atom preparation (+ zeroing) ----------
__global__ void prep_kernel(const float* __restrict__ isp, const float* __restrict__ isd,
                            const float* __restrict__ isr, const float* __restrict__ isl,
                            const float* __restrict__ tmask, const int* __restrict__ npt) {
    int b = blockIdx.x;
    int tid = threadIdx.x;

    // zero all atomic accumulators for this batch (same stream => ordered)
    if (tid < 5)  g_acc[b][tid] = 0.0;
    if (tid < 17) g_mom[b][tid] = 0.0;
    if (tid == 0) g_mse[b] = 0.0;

    __shared__ int   cum[NTOK];
    __shared__ float s_nuc[NTOK], s_w[NTOK], s_a[NTOK], s_b[NTOK];

    float tm = tmask[b * NTOK + tid];
    float dv = isd[b * NTOK + tid];
    float rv = isr[b * NTOK + tid];
    float lv = isl[b * NTOK + tid];
    float pv = isp[b * NTOK + tid];

    s_nuc[tid] = (dv + rv) * tm;
    s_w[tid]   = (1.0f + 5.0f * dv + 5.0f * rv + 10.0f * lv) * tm;
    s_a[tid]   = lv * tm;
    s_b[tid]   = (pv + dv + rv) * tm;
    cum[tid]   = npt[b * NTOK + tid];
    __syncthreads();

    // inclusive scan (Hillis-Steele)
    for (int off = 1; off < NTOK; off <<= 1) {
        int v = (tid >= off) ? cum[tid - off] : 0;
        __syncthreads();
        cum[tid] += v;
        __syncthreads();
    }
    int total = cum[NTOK - 1];

    for (int k = 0; k < NATOM / NTOK; k++) {
        int l = k * NTOK + tid;
        if (l < total) {
            int lo = 0, hi = NTOK - 1;
            while (lo < hi) {
                int mid = (lo + hi) >> 1;
                if (cum[mid] > l) hi = mid; else lo = mid + 1;
            }
            g_tok[b][l]   = lo;
            g_isnuc[b][l] = s_nuc[lo];
            g_watom[b][l] = s_w[lo];
            g_aL[b][l]    = s_a[lo];
            g_bL[b][l]    = s_b[lo];
        } else {
            g_tok[b][l] = 0;
            g_isnuc[b][l] = 0.0f; g_watom[b][l] = 0.0f;
            g_aL[b][l] = 0.0f;    g_bL[b][l] = 0.0f;
        }
    }
}

// ---------------- main pairwise kernel: bond loss + smooth LDDT ----------
__global__ void pair_kernel(const float* __restrict__ x, const float* __restrict__ gt,
                            const float* __restrict__ gmask, const float* __restrict__ tb) {
    int b    = blockIdx.y;
    int row0 = blockIdx.x * ROWS;
    int tid  = threadIdx.x;

    __shared__ float rx[ROWS][3], rg[ROWS][3];
    __shared__ float rm[ROWS], rnuc[ROWS], raL[ROWS];
    __shared__ int   rtok[ROWS];

    const float* xb  = x  + (size_t)b * NATOM * 3;
    const float* gb  = gt + (size_t)b * NATOM * 3;
    const float* mb  = gmask + (size_t)b * NATOM;
    const float* tbb = tb + (size_t)b * NTOK * NTOK;

    if (tid < ROWS) {
        int l = row0 + tid;
        rx[tid][0] = xb[3*l+0]; rx[tid][1] = xb[3*l+1]; rx[tid][2] = xb[3*l+2];
        rg[tid][0] = gb[3*l+0]; rg[tid][1] = gb[3*l+1]; rg[tid][2] = gb[3*l+2];
        rm[tid]   = mb[l];
        rnuc[tid] = g_isnuc[b][l];
        raL[tid]  = g_aL[b][l];
        rtok[tid] = g_tok[b][l];
    }
    __syncthreads();

    const float C05 = 0.60653066f;   // e^-0.5
    const float C1  = 0.36787944f;   // e^-1
    const float C2  = 0.13533528f;   // e^-2
    const float C4  = 0.018315639f;  // e^-4

    float a0 = 0.f, a1 = 0.f, a2 = 0.f, a3 = 0.f, a4 = 0.f;

    for (int ci = 0; ci < NATOM / NTHREADS; ci++) {
        int m = ci * NTHREADS + tid;
        float cx0 = xb[3*m+0], cx1 = xb[3*m+1], cx2 = xb[3*m+2];
        float cg0 = gb[3*m+0], cg1 = gb[3*m+1], cg2 = gb[3*m+2];
        float cm  = mb[m];
        float cbL = g_bL[b][m];
        int   ctk = g_tok[b][m];

        #pragma unroll
        for (int r = 0; r < ROWS; r++) {
            float d0 = rx[r][0] - cx0, d1 = rx[r][1] - cx1, d2c = rx[r][2] - cx2;
            float dd = fmaf(d0, d0, fmaf(d1, d1, d2c * d2c));
            float dxv = sqrtf(dd + 1e-12f);

            float e0 = rg[r][0] - cg0, e1 = rg[r][1] - cg1, e2 = rg[r][2] - cg2;
            float gg = fmaf(e0, e0, fmaf(e1, e1, e2 * e2));
            float dgv = sqrtf(gg + 1e-12f);

            float pm   = rm[r] * cm;
            float wb   = raL[r] * cbL * __ldg(&tbb[rtok[r] * NTOK + ctk]) * pm;
            float diff = dxv - dgv;
            a0 = fmaf(diff * diff, wb, a0);
            a1 += wb;

            float d  = fabsf(diff);
            float E  = __expf(d);
            float e  = 0.25f * (__fdividef(1.f, fmaf(E, C05, 1.f))
                              + __fdividef(1.f, fmaf(E, C1,  1.f))
                              + __fdividef(1.f, fmaf(E, C2,  1.f))
                              + __fdividef(1.f, fmaf(E, C4,  1.f)));

            float lt30 = (dgv < 30.f) ? 1.f : 0.f;
            float lt15 = (dgv < 15.f) ? 1.f : 0.f;
            float c    = fmaf(rnuc[r], lt30 - lt15, lt15);
            float m2   = ((row0 + r) != m) ? pm : 0.f;

            a2 = fmaf(c * e, m2, a2);
            a3 = fmaf(c, m2, a3);
            a4 += m2;
        }
    }

    // block reduction -> atomicAdd double
    __shared__ float red[8][5];
    int lane = tid & 31, w = tid >> 5;
    float vals[5] = {a0, a1, a2, a3, a4};
    #pragma unroll
    for (int k = 0; k < 5; k++) {
        float v = vals[k];
        for (int off = 16; off > 0; off >>= 1) v += __shfl_xor_sync(0xffffffffu, v, off);
        if (lane == 0) red[w][k] = v;
    }
    __syncthreads();
    if (tid < 5) {
        float s = 0.f;
        #pragma unroll
        for (int ww = 0; ww < 8; ww++) s += red[ww][tid];
        atomicAdd(&g_acc[b][tid], (double)s);
    }
}

// ---------------- weighted moment sums for Kabsch (1 atom / thread) ------
__global__ void moments_kernel(const float* __restrict__ x, const float* __restrict__ gt,
                               const float* __restrict__ gmask) {
    int b = blockIdx.y, tid = threadIdx.x;
    int l = blockIdx.x * NTHREADS + tid;
    const float* xb = x  + (size_t)b * NATOM * 3;
    const float* gb = gt + (size_t)b * NATOM * 3;

    float mk = gmask[(size_t)b * NATOM + l];
    float wm = g_watom[b][l] * mk;
    float x0 = xb[3*l+0], x1 = xb[3*l+1], x2 = xb[3*l+2];
    float g0 = gb[3*l+0], g1 = gb[3*l+1], g2 = gb[3*l+2];

    double s[17];
    s[0] = wm;  s[1] = mk;
    s[2] = wm*x0; s[3] = wm*x1; s[4] = wm*x2;
    s[5] = wm*g0; s[6] = wm*g1; s[7] = wm*g2;
    s[8]  = (double)wm*x0*g0; s[9]  = (double)wm*x0*g1; s[10] = (double)wm*x0*g2;
    s[11] = (double)wm*x1*g0; s[12] = (double)wm*x1*g1; s[13] = (double)wm*x1*g2;
    s[14] = (double)wm*x2*g0; s[15] = (double)wm*x2*g1; s[16] = (double)wm*x2*g2;

    __shared__ double red[8][17];
    int lane = tid & 31, w = tid >> 5;
    #pragma unroll
    for (int q = 0; q < 17; q++) {
        double v = s[q];
        for (int off = 16; off > 0; off >>= 1) v += __shfl_xor_sync(0xffffffffu, v, off);
        if (lane == 0) red[w][q] = v;
    }
    __syncthreads();
    if (tid < 17) {
        double v = 0.0;
        #pragma unroll
        for (int ww = 0; ww < 8; ww++) v += red[ww][tid];
        atomicAdd(&g_mom[b][tid], v);
    }
}

// ---------------- QCP Kabsch: Newton on quartic + adjugate eigvec --------
__device__ __forceinline__ double det3(double a00, double a01, double a02,
                                       double a10, double a11, double a12,
                                       double a20, double a21, double a22) {
    return a00*(a11*a22 - a12*a21) - a01*(a10*a22 - a12*a20) + a02*(a10*a21 - a11*a20);
}

__global__ void kabsch_kernel() {
    int b = threadIdx.x;
    if (b >= BATCH) return;

    double W = g_mom[b][0];
    double invW = 1.0 / W;
    double sx[3] = {g_mom[b][2], g_mom[b][3], g_mom[b][4]};
    double sg[3] = {g_mom[b][5], g_mom[b][6], g_mom[b][7]};
    double H[3][3];
    for (int i = 0; i < 3; i++)
        for (int j = 0; j < 3; j++)
            H[i][j] = g_mom[b][8 + i * 3 + j] - sx[i] * sg[j] * invW;
    double mux[3] = {sx[0]*invW, sx[1]*invW, sx[2]*invW};
    double mug[3] = {sg[0]*invW, sg[1]*invW, sg[2]*invW};

    // Horn: S_ij = sum gt_i x_j = H[j][i]
    double Sxx = H[0][0], Sxy = H[1][0], Sxz = H[2][0];
    double Syx = H[0][1], Syy = H[1][1], Syz = H[2][1];
    double Szx = H[0][2], Szy = H[1][2], Szz = H[2][2];

    double N[4][4] = {
        { Sxx+Syy+Szz,  Syz-Szy,       Szx-Sxz,       Sxy-Syx      },
        { Syz-Szy,      Sxx-Syy-Szz,   Sxy+Syx,       Szx+Sxz      },
        { Szx-Sxz,      Sxy+Syx,      -Sxx+Syy-Szz,   Syz+Szy      },
        { Sxy-Syx,      Szx+Sxz,       Syz+Szy,      -Sxx-Syy+Szz  }};

    // characteristic polynomial of traceless symmetric N:
    // p(l) = l^4 + a2 l^2 + a1 l + a0
    double N2[4][4];
    double t2 = 0.0, t3 = 0.0, t4 = 0.0;
    for (int i = 0; i < 4; i++)
        for (int j = 0; j < 4; j++) {
            double v = 0.0;
            for (int k = 0; k < 4; k++) v += N[i][k] * N[k][j];
            N2[i][j] = v;
        }
    for (int i = 0; i < 4; i++)
        for (int j = 0; j < 4; j++) {
            t2 += N[i][j] * N[i][j];
            t3 += N2[i][j] * N[i][j];   // tr(N^3), N symmetric
            t4 += N2[i][j] * N2[i][j];  // tr(N^4)
        }
    double a2 = -0.5 * t2;
    double a1 = -t3 / 3.0;
    double a0 = t2 * t2 / 8.0 - 0.25 * t4;

    // Newton from above (lambda_max <= sqrt(t2)); monotone convergence
    double lam = sqrt(t2);
    for (int it = 0; it < 60; it++) {
        double p  = ((lam * lam + a2) * lam + a1) * lam + a0;
        double dp = (4.0 * lam * lam + 2.0 * a2) * lam + a1;
        if (fabs(dp) < 1e-300) break;
        double step = p / dp;
        lam -= step;
        if (fabs(step) < 1e-14 * (fabs(lam) + 1.0)) break;
    }

    // eigenvector = column of adjugate(N - lam*I) with largest norm
    double M[4][4];
    for (int i = 0; i < 4; i++)
        for (int j = 0; j < 4; j++) M[i][j] = N[i][j] - ((i == j) ? lam : 0.0);

    double adj[4][4];
    int rows[4][3] = {{1,2,3},{0,2,3},{0,1,3},{0,1,2}};
    for (int i = 0; i < 4; i++) {
        for (int j = 0; j < 4; j++) {
            int* rr = rows[j];  // minor removes row j, col i  -> adj[i][j] = cof(j,i)
            int* cc = rows[i];
            double m3 = det3(M[rr[0]][cc[0]], M[rr[0]][cc[1]], M[rr[0]][cc[2]],
                             M[rr[1]][cc[0]], M[rr[1]][cc[1]], M[rr[1]][cc[2]],
                             M[rr[2]][cc[0]], M[rr[2]][cc[1]], M[rr[2]][cc[2]]);
            double sgn = (((i + j) & 1) ? -1.0 : 1.0);
            adj[i][j] = sgn * m3;
        }
    }
    int bestc = 0; double bestn = -1.0;
    for (int j = 0; j < 4; j++) {
        double nn = 0.0;
        for (int i = 0; i < 4; i++) nn += adj[i][j] * adj[i][j];
        if (nn > bestn) { bestn = nn; bestc = j; }
    }
    double q[4];
    double qn = 1.0 / sqrt(bestn);
    for (int i = 0; i < 4; i++) q[i] = adj[i][bestc] * qn;

    double qw = q[0], qx = q[1], qy = q[2], qz = q[3];
    double R[3][3] = {
        {1.0-2.0*(qy*qy+qz*qz), 2.0*(qx*qy-qw*qz),     2.0*(qx*qz+qw*qy)},
        {2.0*(qx*qy+qw*qz),     1.0-2.0*(qx*qx+qz*qz), 2.0*(qy*qz-qw*qx)},
        {2.0*(qx*qz-qw*qy),     2.0*(qy*qz+qw*qx),     1.0-2.0*(qx*qx+qy*qy)}};

    // orientation self-check: maximize <R, H>
    double f1 = 0.0, f2 = 0.0;
    for (int i = 0; i < 3; i++)
        for (int j = 0; j < 3; j++) { f1 += R[i][j]*H[i][j]; f2 += R[j][i]*H[i][j]; }
    if (f2 > f1) {
        for (int i = 0; i < 3; i++)
            for (int j = i + 1; j < 3; j++) { double tmp = R[i][j]; R[i][j] = R[j][i]; R[j][i] = tmp; }
    }

    for (int i = 0; i < 3; i++)
        for (int j = 0; j < 3; j++) g_Rot[b][i*3+j] = (float)R[i][j];
    for (int i = 0; i < 3; i++) { g_Rot[b][9+i] = (float)mug[i]; g_Rot[b][12+i] = (float)mux[i]; }
}

// ---------------- weighted MSE against aligned gt (1 atom / thread) ------
__global__ void mse_kernel(const float* __restrict__ x, const float* __restrict__ gt,
                           const float* __restrict__ gmask) {
    int b = blockIdx.y, tid = threadIdx.x;
    int l = blockIdx.x * NTHREADS + tid;
    const float* xb = x  + (size_t)b * NATOM * 3;
    const float* gb = gt + (size_t)b * NATOM * 3;

    float R00 = g_Rot[b][0], R01 = g_Rot[b][1], R02 = g_Rot[b][2];
    float R10 = g_Rot[b][3], R11 = g_Rot[b][4], R12 = g_Rot[b][5];
    float R20 = g_Rot[b][6], R21 = g_Rot[b][7], R22 = g_Rot[b][8];
    float mg0 = g_Rot[b][9],  mg1 = g_Rot[b][10], mg2 = g_Rot[b][11];
    float mx0 = g_Rot[b][12], mx1 = g_Rot[b][13], mx2 = g_Rot[b][14];

    float g0 = gb[3*l+0] - mg0, g1 = gb[3*l+1] - mg1, g2 = gb[3*l+2] - mg2;
    float a0 = R00*g0 + R01*g1 + R02*g2 + mx0;
    float a1 = R10*g0 + R11*g1 + R12*g2 + mx1;
    float a2 = R20*g0 + R21*g1 + R22*g2 + mx2;
    float d0 = xb[3*l+0] - a0, d1 = xb[3*l+1] - a1, d2 = xb[3*l+2] - a2;
    float e = d0*d0 + d1*d1 + d2*d2;
    double s = (double)(e * g_watom[b][l] * gmask[(size_t)b * NATOM + l]);

    __shared__ double red[8];
    int lane = tid & 31, w = tid >> 5;
    for (int off = 16; off > 0; off >>= 1) s += __shfl_xor_sync(0xffffffffu, s, off);
    if (lane == 0) red[w] = s;
    __syncthreads();
    if (tid == 0) {
        double v = 0.0;
        #pragma unroll
        for (int ww = 0; ww < 8; ww++) v += red[ww];
        atomicAdd(&g_mse[b], v);
    }
}

// ---------------- combine -------------------------------------------------
__global__ void final_kernel(const float* __restrict__ t, float* __restrict__ out) {
    double loss = 0.0;
    for (int b = 0; b < BATCH; b++) {
        double lbond = g_acc[b][0] / g_acc[b][1];
        double ce_m  = g_acc[b][2] / g_acc[b][4];
        double c_m   = g_acc[b][3] / g_acc[b][4];
        double llddt = 1.0 - ce_m / c_m;
        double lmse  = (g_mse[b] / g_mom[b][1]) * (1.0 / 3.0);
        double tv = (double)t[b];
        double wt = (tv * tv + 256.0) / ((tv + 16.0) * (tv + 16.0));
        loss += wt * (lmse + lbond) + llddt;
    }
    out[0] = (float)(loss / BATCH);
}

// ---------------- launch ---------------------------------------------------
extern "C" void kernel_launch(void* const* d_in, const int* in_sizes, int n_in,
                              void* d_out, int out_size) {
    const float* x   = (const float*)d_in[0];
    const float* gt  = (const float*)d_in[1];
    const float* gm  = (const float*)d_in[2];
    const float* isp = (const float*)d_in[3];
    const float* isd = (const float*)d_in[4];
    const float* isr = (const float*)d_in[5];
    const float* isl = (const float*)d_in[6];
    const float* tb  = (const float*)d_in[7];
    const float* tm  = (const float*)d_in[8];
    const int*   npt = (const int*)d_in[9];
    const float* t   = (const float*)d_in[10];
    float* out = (float*)d_out;

    prep_kernel<<<BATCH, NTOK>>>(isp, isd, isr, isl, tm, npt);
    pair_kernel<<<dim3(NATOM / ROWS, BATCH), NTHREADS>>>(x, gt, gm, tb);
    moments_kernel<<<dim3(NATOM / NTHREADS, BATCH), NTHREADS>>>(x, gt, gm);
    kabsch_kernel<<<1, 32>>>();
    mse_kernel<<<dim3(NATOM / NTHREADS, BATCH), NTHREADS>>>(x, gt, gm);
    final_kernel<<<1, 1>>>(t, out);
}

// round 3
// speedup vs baseline: 11.1744x; 1.1542x over previous
#include <cuda_runtime.h>
#include <math.h>

#define BATCH 2
#define NTOK 256
#define NATOM 2048
#define ROWS 8
#define NTHREADS 256

// ---------------- device scratch (no allocations allowed) ----------------
__device__ double g_acc[BATCH][5];     // bond_num, bond_den, ce, csum, msum
__device__ double g_mom[BATCH][17];    // W, Mask, Swx[3], Swg[3], Sxg[9]
__device__ double g_mse[BATCH];
__device__ float  g_Rot[BATCH][15];    // R[9], mu_g[3], mu_x[3]
__device__ float4 g_rowx[BATCH][NATOM];   // x0,x1,x2, mask
__device__ float4 g_rowg[BATCH][NATOM];   // g0,g1,g2, isnuc
__device__ float  g_watom[BATCH][NATOM];
__device__ float  g_aL[BATCH][NATOM];     // is_ligand * tm
__device__ float  g_bL[BATCH][NATOM];     // is_poly   * tm
__device__ int    g_tokN[BATCH][NATOM];   // tok * NTOK

__device__ __forceinline__ float sqrt_approx(float v) {
    float y; asm("sqrt.approx.f32 %0, %1;" : "=f"(y) : "f"(v)); return y;
}

// ---------------- prep: token->atom maps + zeroing + Kabsch moments ------
__global__ void prep_kernel(const float* __restrict__ x, const float* __restrict__ gt,
                            const float* __restrict__ gmask,
                            const float* __restrict__ isp, const float* __restrict__ isd,
                            const float* __restrict__ isr, const float* __restrict__ isl,
                            const float* __restrict__ tmask, const int* __restrict__ npt) {
    int b = blockIdx.x;
    int tid = threadIdx.x;

    if (tid < 5) g_acc[b][tid] = 0.0;   // pair_kernel atomics (ordered: same stream)

    __shared__ int   cum[NTOK];
    __shared__ float s_nuc[NTOK], s_w[NTOK], s_a[NTOK], s_b[NTOK];

    float tm = tmask[b * NTOK + tid];
    float dv = isd[b * NTOK + tid];
    float rv = isr[b * NTOK + tid];
    float lv = isl[b * NTOK + tid];
    float pv = isp[b * NTOK + tid];

    s_nuc[tid] = (dv + rv) * tm;
    s_w[tid]   = (1.0f + 5.0f * dv + 5.0f * rv + 10.0f * lv) * tm;
    s_a[tid]   = lv * tm;
    s_b[tid]   = (pv + dv + rv) * tm;
    cum[tid]   = npt[b * NTOK + tid];
    __syncthreads();

    for (int off = 1; off < NTOK; off <<= 1) {
        int v = (tid >= off) ? cum[tid - off] : 0;
        __syncthreads();
        cum[tid] += v;
        __syncthreads();
    }
    int total = cum[NTOK - 1];

    const float* xb = x  + (size_t)b * NATOM * 3;
    const float* gb = gt + (size_t)b * NATOM * 3;
    const float* mb = gmask + (size_t)b * NATOM;

    double s[17];
    #pragma unroll
    for (int q = 0; q < 17; q++) s[q] = 0.0;

    for (int k = 0; k < NATOM / NTOK; k++) {
        int l = k * NTOK + tid;
        float w_at = 0.f, nuc = 0.f, aL = 0.f, bL = 0.f;
        int tok = 0;
        if (l < total) {
            int lo = 0, hi = NTOK - 1;
            while (lo < hi) {
                int mid = (lo + hi) >> 1;
                if (cum[mid] > l) hi = mid; else lo = mid + 1;
            }
            tok = lo; nuc = s_nuc[lo]; w_at = s_w[lo]; aL = s_a[lo]; bL = s_b[lo];
        }
        float mk = mb[l];
        float x0 = xb[3*l+0], x1 = xb[3*l+1], x2 = xb[3*l+2];
        float g0 = gb[3*l+0], g1 = gb[3*l+1], g2 = gb[3*l+2];

        g_rowx[b][l]  = make_float4(x0, x1, x2, mk);
        g_rowg[b][l]  = make_float4(g0, g1, g2, nuc);
        g_watom[b][l] = w_at;
        g_aL[b][l]    = aL;
        g_bL[b][l]    = bL;
        g_tokN[b][l]  = tok * NTOK;

        double wm = (double)(w_at * mk);
        s[0] += wm; s[1] += (double)mk;
        s[2] += wm*x0; s[3] += wm*x1; s[4] += wm*x2;
        s[5] += wm*g0; s[6] += wm*g1; s[7] += wm*g2;
        s[8]  += wm*x0*g0; s[9]  += wm*x0*g1; s[10] += wm*x0*g2;
        s[11] += wm*x1*g0; s[12] += wm*x1*g1; s[13] += wm*x1*g2;
        s[14] += wm*x2*g0; s[15] += wm*x2*g1; s[16] += wm*x2*g2;
    }

    __shared__ double red[8][17];
    int lane = tid & 31, w = tid >> 5;
    #pragma unroll
    for (int q = 0; q < 17; q++) {
        double v = s[q];
        for (int off = 16; off > 0; off >>= 1) v += __shfl_xor_sync(0xffffffffu, v, off);
        if (lane == 0) red[w][q] = v;
    }
    __syncthreads();
    if (tid < 17) {
        double v = 0.0;
        #pragma unroll
        for (int ww = 0; ww < 8; ww++) v += red[ww][tid];
        g_mom[b][tid] = v;
    }
}

// ---------------- main pairwise kernel: bond loss + smooth LDDT ----------
// smooth-lddt e(d) = 0.25*sum_a sigmoid(a-d), a in {0.5,1,2,4}
//            = P(E)/Q(E), E = exp(d)   (exact rational identity)
__global__ void pair_kernel(const float* __restrict__ tb) {
    int b    = blockIdx.y;
    int row0 = blockIdx.x * ROWS;
    int tid  = threadIdx.x;

    __shared__ float4 srx[ROWS], srg[ROWS];
    __shared__ float  sraL[ROWS];
    __shared__ int    srtokN[ROWS];

    const float* tbb = tb + (size_t)b * NTOK * NTOK;

    if (tid < ROWS) {
        int l = row0 + tid;
        srx[tid]    = g_rowx[b][l];
        srg[tid]    = g_rowg[b][l];
        sraL[tid]   = g_aL[b][l];
        srtokN[tid] = g_tokN[b][l];
    }
    __syncthreads();

    // numerator / denominator coefficients (0.25 folded into numerator)
    const float n1 = 0.846045767f,  n2 = 0.187663961f,  n3 = 0.0091748690f;
    const float d1 = 1.128061023f,  d2 = 0.375327923f,  d3 = 0.036699476f, d4 = 0.00055308437f;

    float a0 = 0.f, a1 = 0.f, a2 = 0.f, a3 = 0.f, a4 = 0.f;

    for (int ci = 0; ci < NATOM / NTHREADS; ci++) {
        int m = ci * NTHREADS + tid;
        float4 cx = g_rowx[b][m];      // x0,x1,x2,mask
        float4 cg = g_rowg[b][m];      // g0,g1,g2,nuc (nuc unused col-side)
        float  cbL = g_bL[b][m];
        int    ctk = g_tokN[b][m];     // unused col-side (row tok used); keep for bond
        (void)ctk;
        int    mtok = 0;
        // column token index for bond lookup:
        mtok = g_tokN[b][m] / NTOK;

        #pragma unroll
        for (int r = 0; r < ROWS; r++) {
            float4 rx = srx[r];
            float4 rg = srg[r];

            float dd0 = rx.x - cx.x, dd1 = rx.y - cx.y, dd2 = rx.z - cx.z;
            float dxv = sqrt_approx(fmaf(dd0, dd0, fmaf(dd1, dd1, fmaf(dd2, dd2, 1e-12f))));

            float ee0 = rg.x - cg.x, ee1 = rg.y - cg.y, ee2 = rg.z - cg.z;
            float dgv = sqrt_approx(fmaf(ee0, ee0, fmaf(ee1, ee1, fmaf(ee2, ee2, 1e-12f))));

            float pm   = rx.w * cx.w;
            float wb   = sraL[r] * cbL * __ldg(&tbb[srtokN[r] + mtok]) * pm;
            float diff = dxv - dgv;
            a0 = fmaf(diff * diff, wb, a0);
            a1 += wb;

            float d = fminf(fabsf(diff), 20.f);
            float E = __expf(d);
            float num = fmaf(fmaf(fmaf(n3, E, n2), E, n1), E, 1.f);
            float den = fmaf(fmaf(fmaf(fmaf(d4, E, d3), E, d2), E, d1), E, 1.f);
            float e   = __fdividef(num, den);

            float c;
            if (dgv < 15.f)      c = 1.f;
            else if (dgv < 30.f) c = rg.w;   // row isnuc
            else                 c = 0.f;

            float m2  = ((row0 + r) != m) ? pm : 0.f;
            float cm2 = c * m2;

            a2 = fmaf(cm2, e, a2);
            a3 += cm2;
            a4 += m2;
        }
    }

    __shared__ float red[8][5];
    int lane = tid & 31, w = tid >> 5;
    float vals[5] = {a0, a1, a2, a3, a4};
    #pragma unroll
    for (int k = 0; k < 5; k++) {
        float v = vals[k];
        for (int off = 16; off > 0; off >>= 1) v += __shfl_xor_sync(0xffffffffu, v, off);
        if (lane == 0) red[w][k] = v;
    }
    __syncthreads();
    if (tid < 5) {
        float ssum = 0.f;
        #pragma unroll
        for (int ww = 0; ww < 8; ww++) ssum += red[ww][tid];
        atomicAdd(&g_acc[b][tid], (double)ssum);
    }
}

// ---------------- QCP Kabsch: normalized fp32 Newton + adjugate ----------
__device__ __forceinline__ float det3f(float a00, float a01, float a02,
                                       float a10, float a11, float a12,
                                       float a20, float a21, float a22) {
    return a00*(a11*a22 - a12*a21) - a01*(a10*a22 - a12*a20) + a02*(a10*a21 - a11*a20);
}

__global__ void kabsch_kernel() {
    int b = threadIdx.x;
    if (b >= BATCH) return;

    double W = g_mom[b][0];
    double invW = 1.0 / W;
    double sx[3] = {g_mom[b][2], g_mom[b][3], g_mom[b][4]};
    double sg[3] = {g_mom[b][5], g_mom[b][6], g_mom[b][7]};
    double H[3][3];
    for (int i = 0; i < 3; i++)
        for (int j = 0; j < 3; j++)
            H[i][j] = g_mom[b][8 + i * 3 + j] - sx[i] * sg[j] * invW;
    double mux[3] = {sx[0]*invW, sx[1]*invW, sx[2]*invW};
    double mug[3] = {sg[0]*invW, sg[1]*invW, sg[2]*invW};

    // Horn: S_ij = sum gt_i x_j = H[j][i]
    double Sxx = H[0][0], Sxy = H[1][0], Sxz = H[2][0];
    double Syx = H[0][1], Syy = H[1][1], Syz = H[2][1];
    double Szx = H[0][2], Szy = H[1][2], Szz = H[2][2];

    double Nd[4][4] = {
        { Sxx+Syy+Szz,  Syz-Szy,       Szx-Sxz,       Sxy-Syx      },
        { Syz-Szy,      Sxx-Syy-Szz,   Sxy+Syx,       Szx+Sxz      },
        { Szx-Sxz,      Sxy+Syx,      -Sxx+Syy-Szz,   Syz+Szy      },
        { Sxy-Syx,      Szx+Sxz,       Syz+Szy,      -Sxx-Syy+Szz  }};

    // normalize so that tr(N^2) = 1  => do eigen work in fp32
    double fro = 0.0;
    for (int i = 0; i < 4; i++) for (int j = 0; j < 4; j++) fro += Nd[i][j]*Nd[i][j];
    double scl = 1.0 / sqrt(fro + 1e-300);

    float N[4][4];
    for (int i = 0; i < 4; i++)
        for (int j = 0; j < 4; j++) N[i][j] = (float)(Nd[i][j] * scl);

    float N2[4][4];
    float t3 = 0.f, t4 = 0.f;
    #pragma unroll
    for (int i = 0; i < 4; i++)
        #pragma unroll
        for (int j = 0; j < 4; j++) {
            float v = 0.f;
            #pragma unroll
            for (int k = 0; k < 4; k++) v = fmaf(N[i][k], N[k][j], v);
            N2[i][j] = v;
        }
    #pragma unroll
    for (int i = 0; i < 4; i++)
        #pragma unroll
        for (int j = 0; j < 4; j++) {
            t3 = fmaf(N2[i][j], N[i][j], t3);
            t4 = fmaf(N2[i][j], N2[i][j], t4);
        }
    const float a2c = -0.5f;
    float a1c = -t3 * (1.f / 3.f);
    float a0c = 0.125f - 0.25f * t4;

    // Newton from above (lam_max <= 1 after normalization)
    float lam = 1.0f;
    #pragma unroll
    for (int it = 0; it < 16; it++) {
        float p  = fmaf(fmaf(fmaf(lam, lam, a2c), lam, a1c), lam, a0c);
        float dp = fmaf(fmaf(4.f, lam * lam, 2.f * a2c), lam, a1c);
        lam -= __fdividef(p, dp);
    }

    // eigenvector = max-norm column of adjugate(N - lam I)
    float M[4][4];
    for (int i = 0; i < 4; i++)
        for (int j = 0; j < 4; j++) M[i][j] = N[i][j] - ((i == j) ? lam : 0.f);

    float adj[4][4];
    const int rows[4][3] = {{1,2,3},{0,2,3},{0,1,3},{0,1,2}};
    #pragma unroll
    for (int i = 0; i < 4; i++) {
        #pragma unroll
        for (int j = 0; j < 4; j++) {
            const int* rr = rows[j];
            const int* cc = rows[i];
            float m3 = det3f(M[rr[0]][cc[0]], M[rr[0]][cc[1]], M[rr[0]][cc[2]],
                             M[rr[1]][cc[0]], M[rr[1]][cc[1]], M[rr[1]][cc[2]],
                             M[rr[2]][cc[0]], M[rr[2]][cc[1]], M[rr[2]][cc[2]]);
            adj[i][j] = (((i + j) & 1) ? -m3 : m3);
        }
    }
    int bestc = 0; float bestn = -1.f;
    #pragma unroll
    for (int j = 0; j < 4; j++) {
        float nn = 0.f;
        #pragma unroll
        for (int i = 0; i < 4; i++) nn = fmaf(adj[i][j], adj[i][j], nn);
        if (nn > bestn) { bestn = nn; bestc = j; }
    }
    float qn = __fdividef(1.f, sqrtf(bestn));
    float q0 = adj[0][bestc] * qn, q1 = adj[1][bestc] * qn;
    float q2 = adj[2][bestc] * qn, q3 = adj[3][bestc] * qn;

    float R[3][3] = {
        {1.f-2.f*(q2*q2+q3*q3), 2.f*(q1*q2-q0*q3),     2.f*(q1*q3+q0*q2)},
        {2.f*(q1*q2+q0*q3),     1.f-2.f*(q1*q1+q3*q3), 2.f*(q2*q3-q0*q1)},
        {2.f*(q1*q3-q0*q2),     2.f*(q2*q3+q0*q1),     1.f-2.f*(q1*q1+q2*q2)}};

    // orientation self-check: maximize <R, H>
    float f1 = 0.f, f2 = 0.f;
    for (int i = 0; i < 3; i++)
        for (int j = 0; j < 3; j++) {
            float Hf = (float)(H[i][j] * scl);
            f1 = fmaf(R[i][j], Hf, f1);
            f2 = fmaf(R[j][i], Hf, f2);
        }
    if (f2 > f1) {
        for (int i = 0; i < 3; i++)
            for (int j = i + 1; j < 3; j++) { float tmp = R[i][j]; R[i][j] = R[j][i]; R[j][i] = tmp; }
    }

    for (int i = 0; i < 3; i++)
        for (int j = 0; j < 3; j++) g_Rot[b][i*3+j] = R[i][j];
    for (int i = 0; i < 3; i++) { g_Rot[b][9+i] = (float)mug[i]; g_Rot[b][12+i] = (float)mux[i]; }
}

// ---------------- weighted MSE (single block / batch, no atomics) --------
__global__ void mse_kernel() {
    int b = blockIdx.x, tid = threadIdx.x;

    float R00 = g_Rot[b][0], R01 = g_Rot[b][1], R02 = g_Rot[b][2];
    float R10 = g_Rot[b][3], R11 = g_Rot[b][4], R12 = g_Rot[b][5];
    float R20 = g_Rot[b][6], R21 = g_Rot[b][7], R22 = g_Rot[b][8];
    float mg0 = g_Rot[b][9],  mg1 = g_Rot[b][10], mg2 = g_Rot[b][11];
    float mx0 = g_Rot[b][12], mx1 = g_Rot[b][13], mx2 = g_Rot[b][14];

    double s = 0.0;
    for (int k = 0; k < NATOM / NTHREADS; k++) {
        int l = k * NTHREADS + tid;
        float4 rx = g_rowx[b][l];   // x, mask
        float4 rg = g_rowg[b][l];   // gt
        float g0 = rg.x - mg0, g1 = rg.y - mg1, g2 = rg.z - mg2;
        float c0 = R00*g0 + R01*g1 + R02*g2 + mx0;
        float c1 = R10*g0 + R11*g1 + R12*g2 + mx1;
        float c2 = R20*g0 + R21*g1 + R22*g2 + mx2;
        float d0 = rx.x - c0, d1 = rx.y - c1, d2 = rx.z - c2;
        float e = d0*d0 + d1*d1 + d2*d2;
        s += (double)(e * g_watom[b][l] * rx.w);
    }

    __shared__ double red[8];
    int lane = tid & 31, w = tid >> 5;
    for (int off = 16; off > 0; off >>= 1) s += __shfl_xor_sync(0xffffffffu, s, off);
    if (lane == 0) red[w] = s;
    __syncthreads();
    if (tid == 0) {
        double v = 0.0;
        #pragma unroll
        for (int ww = 0; ww < 8; ww++) v += red[ww];
        g_mse[b] = v;
    }
}

// ---------------- combine -------------------------------------------------
__global__ void final_kernel(const float* __restrict__ t, float* __restrict__ out) {
    double loss = 0.0;
    for (int b = 0; b < BATCH; b++) {
        double lbond = g_acc[b][0] / g_acc[b][1];
        double ce_m  = g_acc[b][2] / g_acc[b][4];
        double c_m   = g_acc[b][3] / g_acc[b][4];
        double llddt = 1.0 - ce_m / c_m;
        double lmse  = (g_mse[b] / g_mom[b][1]) * (1.0 / 3.0);
        double tv = (double)t[b];
        double wt = (tv * tv + 256.0) / ((tv + 16.0) * (tv + 16.0));
        loss += wt * (lmse + lbond) + llddt;
    }
    out[0] = (float)(loss / BATCH);
}

// ---------------- launch ---------------------------------------------------
extern "C" void kernel_launch(void* const* d_in, const int* in_sizes, int n_in,
                              void* d_out, int out_size) {
    const float* x   = (const float*)d_in[0];
    const float* gt  = (const float*)d_in[1];
    const float* gm  = (const float*)d_in[2];
    const float* isp = (const float*)d_in[3];
    const float* isd = (const float*)d_in[4];
    const float* isr = (const float*)d_in[5];
    const float* isl = (const float*)d_in[6];
    const float* tb  = (const float*)d_in[7];
    const float* tm  = (const float*)d_in[8];
    const int*   npt = (const int*)d_in[9];
    const float* t   = (const float*)d_in[10];
    float* out = (float*)d_out;

    prep_kernel<<<BATCH, NTOK>>>(x, gt, gm, isp, isd, isr, isl, tm, npt);
    pair_kernel<<<dim3(NATOM / ROWS, BATCH), NTHREADS>>>(tb);
    kabsch_kernel<<<1, 32>>>();
    mse_kernel<<<BATCH, NTHREADS>>>();
    final_kernel<<<1, 1>>>(t, out);
}

// round 4
// speedup vs baseline: 12.2263x; 1.0941x over previous
#include <cuda_runtime.h>
#include <math.h>

#define BATCH 2
#define NTOK 256
#define NATOM 2048
#define NTILE 16            // NATOM / 128
#define NPAIRS 136          // NTILE*(NTILE+1)/2

// ---------------- device scratch (no allocations allowed) ----------------
__device__ double g_acc[BATCH][5];         // bond_num, bond_den, ce, csum, msum
__device__ double g_mom[BATCH][17];        // W, Mask, Swx[3], Swg[3], Sxg[9]
__device__ float4 g_rowx[BATCH][NATOM];    // x0,x1,x2, mask
__device__ float4 g_rowg[BATCH][NATOM];    // g0,g1,g2, isnuc
__device__ float  g_watom[BATCH][NATOM];
__device__ int    g_tok[BATCH][NATOM];
__device__ float  g_S[BATCH][NTOK * NTOK]; // symmetric bond-weight matrix

__device__ __forceinline__ float sqrt_approx(float v) {
    float y; asm("sqrt.approx.f32 %0, %1;" : "=f"(y) : "f"(v)); return y;
}

// ---------------- prep: token->atom maps, moments, bond diagonal ---------
__global__ void prep_kernel(const float* __restrict__ x, const float* __restrict__ gt,
                            const float* __restrict__ gmask,
                            const float* __restrict__ isp, const float* __restrict__ isd,
                            const float* __restrict__ isr, const float* __restrict__ isl,
                            const float* __restrict__ tmask, const int* __restrict__ npt,
                            const float* __restrict__ tb) {
    int b = blockIdx.x;
    int tid = threadIdx.x;

    if (tid == 0) { g_acc[b][0] = 0.0; g_acc[b][2] = 0.0; g_acc[b][3] = 0.0; g_acc[b][4] = 0.0; }

    __shared__ int   cum[NTOK];
    __shared__ float s_nuc[NTOK], s_w[NTOK], s_a[NTOK], s_b[NTOK];

    float tm = tmask[b * NTOK + tid];
    float dv = isd[b * NTOK + tid];
    float rv = isr[b * NTOK + tid];
    float lv = isl[b * NTOK + tid];
    float pv = isp[b * NTOK + tid];

    s_nuc[tid] = (dv + rv) * tm;
    s_w[tid]   = (1.0f + 5.0f * dv + 5.0f * rv + 10.0f * lv) * tm;
    s_a[tid]   = lv * tm;                 // ligand side
    s_b[tid]   = (pv + dv + rv) * tm;     // polymer side
    cum[tid]   = npt[b * NTOK + tid];
    __syncthreads();

    for (int off = 1; off < NTOK; off <<= 1) {
        int v = (tid >= off) ? cum[tid - off] : 0;
        __syncthreads();
        cum[tid] += v;
        __syncthreads();
    }
    int total = cum[NTOK - 1];

    const float* xb = x  + (size_t)b * NATOM * 3;
    const float* gb = gt + (size_t)b * NATOM * 3;
    const float* mb = gmask + (size_t)b * NATOM;
    const float* tbb = tb + (size_t)b * NTOK * NTOK;

    double s[18];
    #pragma unroll
    for (int q = 0; q < 18; q++) s[q] = 0.0;

    for (int k = 0; k < NATOM / NTOK; k++) {
        int l = k * NTOK + tid;
        float w_at = 0.f, nuc = 0.f, aL = 0.f, bL = 0.f;
        int tok = 0;
        if (l < total) {
            int lo = 0, hi = NTOK - 1;
            while (lo < hi) {
                int mid = (lo + hi) >> 1;
                if (cum[mid] > l) hi = mid; else lo = mid + 1;
            }
            tok = lo; nuc = s_nuc[lo]; w_at = s_w[lo]; aL = s_a[lo]; bL = s_b[lo];
        }
        float mk = mb[l];
        float x0 = xb[3*l+0], x1 = xb[3*l+1], x2 = xb[3*l+2];
        float g0 = gb[3*l+0], g1 = gb[3*l+1], g2 = gb[3*l+2];

        g_rowx[b][l]  = make_float4(x0, x1, x2, mk);
        g_rowg[b][l]  = make_float4(g0, g1, g2, nuc);
        g_watom[b][l] = w_at;
        g_tok[b][l]   = tok;

        double wm = (double)(w_at * mk);
        s[0] += wm; s[1] += (double)mk;
        s[2] += wm*x0; s[3] += wm*x1; s[4] += wm*x2;
        s[5] += wm*g0; s[6] += wm*g1; s[7] += wm*g2;
        s[8]  += wm*x0*g0; s[9]  += wm*x0*g1; s[10] += wm*x0*g2;
        s[11] += wm*x1*g0; s[12] += wm*x1*g1; s[13] += wm*x1*g2;
        s[14] += wm*x2*g0; s[15] += wm*x2*g1; s[16] += wm*x2*g2;
        // bond denominator diagonal term (diff == 0 exactly on the diagonal)
        s[17] += (double)(aL * bL * __ldg(&tbb[tok * NTOK + tok]) * mk * mk);
    }

    __shared__ double red[8][18];
    int lane = tid & 31, w = tid >> 5;
    #pragma unroll
    for (int q = 0; q < 18; q++) {
        double v = s[q];
        for (int off = 16; off > 0; off >>= 1) v += __shfl_xor_sync(0xffffffffu, v, off);
        if (lane == 0) red[w][q] = v;
    }
    __syncthreads();
    if (tid < 17) {
        double v = 0.0;
        #pragma unroll
        for (int ww = 0; ww < 8; ww++) v += red[ww][tid];
        g_mom[b][tid] = v;
    }
    if (tid == 17) {
        double v = 0.0;
        #pragma unroll
        for (int ww = 0; ww < 8; ww++) v += red[ww][17];
        g_acc[b][1] = v;   // bond denominator starts at diagonal sum
    }
}

// ---------------- symmetric bond-weight token matrix ----------------------
// S[i][j] = tb[i,j]*a_i*p_j + tb[j,i]*a_j*p_i  (token_mask folded into a,p)
__global__ void sprep_kernel(const float* __restrict__ isp, const float* __restrict__ isd,
                             const float* __restrict__ isr, const float* __restrict__ isl,
                             const float* __restrict__ tmask, const float* __restrict__ tb) {
    int b = blockIdx.y;
    int i = blockIdx.x;
    int j = threadIdx.x;

    const float* base = isl + (size_t)b * NTOK;
    float tmi = tmask[b * NTOK + i], tmj = tmask[b * NTOK + j];
    float ai = base[i] * tmi;
    float aj = base[j] * tmj;
    float pi = (isp[b*NTOK+i] + isd[b*NTOK+i] + isr[b*NTOK+i]) * tmi;
    float pj = (isp[b*NTOK+j] + isd[b*NTOK+j] + isr[b*NTOK+j]) * tmj;

    const float* tbb = tb + (size_t)b * NTOK * NTOK;
    g_S[b][i * NTOK + j] = tbb[i * NTOK + j] * ai * pj + tbb[j * NTOK + i] * aj * pi;
}

// ---------------- pairwise kernel over the upper triangle ----------------
// smooth-lddt e(d) = 0.25*sum_a sigmoid(a-d) = P(E)/Q(E), E = exp(d)
__global__ void pair_kernel() {
    int b = blockIdx.y;
    int p = blockIdx.x;
    int I = 0, rem = p;
    while (rem >= (NTILE - I)) { rem -= (NTILE - I); I++; }
    int J = I + rem;

    __shared__ float4 sx0[128], sg0[128], sx1[128], sg1[128];
    __shared__ int    st0[128], st1[128];

    int tid = threadIdx.x;
    if (tid < 128) {
        int l = I * 128 + tid;
        sx0[tid] = g_rowx[b][l]; sg0[tid] = g_rowg[b][l]; st0[tid] = g_tok[b][l];
    } else {
        int l = J * 128 + (tid - 128);
        sx1[tid-128] = g_rowx[b][l]; sg1[tid-128] = g_rowg[b][l]; st1[tid-128] = g_tok[b][l];
    }
    __syncthreads();

    int r  = tid >> 1;
    int jb = (tid & 1) << 6;
    float4 rx = sx0[r], rg = sg0[r];
    int rS = st0[r] * NTOK;
    const float* Sb = g_S[b];
    bool diag = (I == J);

    const float n1 = 0.846045767f,  n2 = 0.187663961f,  n3 = 0.0091748690f;
    const float d1 = 1.128061023f,  d2 = 0.375327923f,  d3 = 0.036699476f, d4 = 0.00055308437f;

    float a0 = 0.f, a1 = 0.f, a2 = 0.f, a3 = 0.f, a4 = 0.f;

    #pragma unroll 4
    for (int jj = 0; jj < 64; jj++) {
        int j = jb + jj;
        float4 cx = sx1[j], cg = sg1[j];

        float valid = (!diag || (j > r)) ? 1.f : 0.f;
        float pm = rx.w * cx.w * valid;

        float dd0 = rx.x - cx.x, dd1 = rx.y - cx.y, dd2 = rx.z - cx.z;
        float dxv = sqrt_approx(fmaf(dd0, dd0, fmaf(dd1, dd1, fmaf(dd2, dd2, 1e-12f))));

        float ee0 = rg.x - cg.x, ee1 = rg.y - cg.y, ee2 = rg.z - cg.z;
        float dgv = sqrt_approx(fmaf(ee0, ee0, fmaf(ee1, ee1, fmaf(ee2, ee2, 1e-12f))));

        float diff = dxv - dgv;
        float wbs = __ldg(&Sb[rS + st1[j]]) * pm;   // both directions folded
        a0 = fmaf(diff * diff, wbs, a0);
        a1 += wbs;

        float d = fminf(fabsf(diff), 20.f);
        float E = __expf(d);
        float num = fmaf(fmaf(fmaf(n3, E, n2), E, n1), E, 1.f);
        float den = fmaf(fmaf(fmaf(fmaf(d4, E, d3), E, d2), E, d1), E, 1.f);
        float e   = __fdividef(num, den);

        float lt15 = (dgv < 15.f) ? 1.f : 0.f;
        float lt30 = (dgv < 30.f) ? 1.f : 0.f;
        // c(i,j)+c(j,i) = 2*lt15 + (nuc_i + nuc_j)*(lt30 - lt15)
        float csum = fmaf(rg.w + cg.w, lt30 - lt15, 2.f * lt15) * pm;

        a2 = fmaf(csum, e, a2);
        a3 += csum;
        a4 += 2.f * pm;
    }

    __shared__ float red[8][5];
    int lane = tid & 31, w = tid >> 5;
    float vals[5] = {a0, a1, a2, a3, a4};
    #pragma unroll
    for (int k = 0; k < 5; k++) {
        float v = vals[k];
        for (int off = 16; off > 0; off >>= 1) v += __shfl_xor_sync(0xffffffffu, v, off);
        if (lane == 0) red[w][k] = v;
    }
    __syncthreads();
    if (tid < 5) {
        float ssum = 0.f;
        #pragma unroll
        for (int ww = 0; ww < 8; ww++) ssum += red[ww][tid];
        atomicAdd(&g_acc[b][tid], (double)ssum);
    }
}

// ---------------- fused tail: QCP Kabsch + weighted MSE + final ----------
__device__ __forceinline__ float det3f(float a00, float a01, float a02,
                                       float a10, float a11, float a12,
                                       float a20, float a21, float a22) {
    return a00*(a11*a22 - a12*a21) - a01*(a10*a22 - a12*a20) + a02*(a10*a21 - a11*a20);
}

__global__ void tail_kernel(const float* __restrict__ t, float* __restrict__ out) {
    __shared__ float sR[BATCH][15];
    __shared__ double sred[16];
    int tid = threadIdx.x;   // 512 threads

    if (tid < BATCH) {
        int b = tid;
        double W = g_mom[b][0];
        double invW = 1.0 / W;
        double sx[3] = {g_mom[b][2], g_mom[b][3], g_mom[b][4]};
        double sg[3] = {g_mom[b][5], g_mom[b][6], g_mom[b][7]};
        double H[3][3];
        for (int i = 0; i < 3; i++)
            for (int j = 0; j < 3; j++)
                H[i][j] = g_mom[b][8 + i * 3 + j] - sx[i] * sg[j] * invW;

        double Sxx = H[0][0], Sxy = H[1][0], Sxz = H[2][0];
        double Syx = H[0][1], Syy = H[1][1], Syz = H[2][1];
        double Szx = H[0][2], Szy = H[1][2], Szz = H[2][2];

        double Nd[4][4] = {
            { Sxx+Syy+Szz,  Syz-Szy,       Szx-Sxz,       Sxy-Syx      },
            { Syz-Szy,      Sxx-Syy-Szz,   Sxy+Syx,       Szx+Sxz      },
            { Szx-Sxz,      Sxy+Syx,      -Sxx+Syy-Szz,   Syz+Szy      },
            { Sxy-Syx,      Szx+Sxz,       Syz+Szy,      -Sxx-Syy+Szz  }};

        double fro = 0.0;
        for (int i = 0; i < 4; i++) for (int j = 0; j < 4; j++) fro += Nd[i][j]*Nd[i][j];
        double scl = 1.0 / sqrt(fro + 1e-300);

        float N[4][4];
        for (int i = 0; i < 4; i++)
            for (int j = 0; j < 4; j++) N[i][j] = (float)(Nd[i][j] * scl);

        float N2[4][4]; float t3 = 0.f, t4 = 0.f;
        #pragma unroll
        for (int i = 0; i < 4; i++)
            #pragma unroll
            for (int j = 0; j < 4; j++) {
                float v = 0.f;
                #pragma unroll
                for (int k = 0; k < 4; k++) v = fmaf(N[i][k], N[k][j], v);
                N2[i][j] = v;
            }
        #pragma unroll
        for (int i = 0; i < 4; i++)
            #pragma unroll
            for (int j = 0; j < 4; j++) {
                t3 = fmaf(N2[i][j], N[i][j], t3);
                t4 = fmaf(N2[i][j], N2[i][j], t4);
            }
        const float a2c = -0.5f;
        float a1c = -t3 * (1.f / 3.f);
        float a0c = 0.125f - 0.25f * t4;

        float lam = 1.0f;
        #pragma unroll
        for (int it = 0; it < 16; it++) {
            float pp = fmaf(fmaf(fmaf(lam, lam, a2c), lam, a1c), lam, a0c);
            float dp = fmaf(fmaf(4.f, lam * lam, 2.f * a2c), lam, a1c);
            lam -= __fdividef(pp, dp);
        }

        float M[4][4];
        for (int i = 0; i < 4; i++)
            for (int j = 0; j < 4; j++) M[i][j] = N[i][j] - ((i == j) ? lam : 0.f);

        float adj[4][4];
        const int rows[4][3] = {{1,2,3},{0,2,3},{0,1,3},{0,1,2}};
        #pragma unroll
        for (int i = 0; i < 4; i++)
            #pragma unroll
            for (int j = 0; j < 4; j++) {
                const int* rr = rows[j];
                const int* cc = rows[i];
                float m3 = det3f(M[rr[0]][cc[0]], M[rr[0]][cc[1]], M[rr[0]][cc[2]],
                                 M[rr[1]][cc[0]], M[rr[1]][cc[1]], M[rr[1]][cc[2]],
                                 M[rr[2]][cc[0]], M[rr[2]][cc[1]], M[rr[2]][cc[2]]);
                adj[i][j] = (((i + j) & 1) ? -m3 : m3);
            }
        int bestc = 0; float bestn = -1.f;
        #pragma unroll
        for (int j = 0; j < 4; j++) {
            float nn = 0.f;
            #pragma unroll
            for (int i = 0; i < 4; i++) nn = fmaf(adj[i][j], adj[i][j], nn);
            if (nn > bestn) { bestn = nn; bestc = j; }
        }
        float qn = __fdividef(1.f, sqrtf(bestn));
        float q0 = adj[0][bestc] * qn, q1 = adj[1][bestc] * qn;
        float q2 = adj[2][bestc] * qn, q3 = adj[3][bestc] * qn;

        float R[3][3] = {
            {1.f-2.f*(q2*q2+q3*q3), 2.f*(q1*q2-q0*q3),     2.f*(q1*q3+q0*q2)},
            {2.f*(q1*q2+q0*q3),     1.f-2.f*(q1*q1+q3*q3), 2.f*(q2*q3-q0*q1)},
            {2.f*(q1*q3-q0*q2),     2.f*(q2*q3+q0*q1),     1.f-2.f*(q1*q1+q2*q2)}};

        float f1 = 0.f, f2 = 0.f;
        for (int i = 0; i < 3; i++)
            for (int j = 0; j < 3; j++) {
                float Hf = (float)(H[i][j] * scl);
                f1 = fmaf(R[i][j], Hf, f1);
                f2 = fmaf(R[j][i], Hf, f2);
            }
        if (f2 > f1) {
            for (int i = 0; i < 3; i++)
                for (int j = i + 1; j < 3; j++) { float tmp = R[i][j]; R[i][j] = R[j][i]; R[j][i] = tmp; }
        }

        for (int i = 0; i < 3; i++)
            for (int j = 0; j < 3; j++) sR[b][i*3+j] = R[i][j];
        for (int i = 0; i < 3; i++) {
            sR[b][9+i]  = (float)(sg[i] * invW);   // mu_gt
            sR[b][12+i] = (float)(sx[i] * invW);   // mu_x
        }
    }
    __syncthreads();

    // weighted MSE: threads [0,256) -> batch 0, [256,512) -> batch 1
    int b  = tid >> 8;
    int at = tid & 255;

    float R00 = sR[b][0], R01 = sR[b][1], R02 = sR[b][2];
    float R10 = sR[b][3], R11 = sR[b][4], R12 = sR[b][5];
    float R20 = sR[b][6], R21 = sR[b][7], R22 = sR[b][8];
    float mg0 = sR[b][9],  mg1 = sR[b][10], mg2 = sR[b][11];
    float mx0 = sR[b][12], mx1 = sR[b][13], mx2 = sR[b][14];

    double s = 0.0;
    for (int k = 0; k < NATOM / 256; k++) {
        int l = k * 256 + at;
        float4 rx = g_rowx[b][l];
        float4 rg = g_rowg[b][l];
        float g0 = rg.x - mg0, g1 = rg.y - mg1, g2 = rg.z - mg2;
        float c0 = R00*g0 + R01*g1 + R02*g2 + mx0;
        float c1 = R10*g0 + R11*g1 + R12*g2 + mx1;
        float c2 = R20*g0 + R21*g1 + R22*g2 + mx2;
        float e0 = rx.x - c0, e1 = rx.y - c1, e2 = rx.z - c2;
        float e = e0*e0 + e1*e1 + e2*e2;
        s += (double)(e * g_watom[b][l] * rx.w);
    }

    int lane = tid & 31, w = tid >> 5;   // warps 0-7 = b0, 8-15 = b1
    for (int off = 16; off > 0; off >>= 1) s += __shfl_xor_sync(0xffffffffu, s, off);
    if (lane == 0) sred[w] = s;
    __syncthreads();

    if (tid == 0) {
        double loss = 0.0;
        for (int bb = 0; bb < BATCH; bb++) {
            double mse = 0.0;
            for (int ww = 0; ww < 8; ww++) mse += sred[bb * 8 + ww];
            double lbond = g_acc[bb][0] / g_acc[bb][1];
            double ce_m  = g_acc[bb][2] / g_acc[bb][4];
            double c_m   = g_acc[bb][3] / g_acc[bb][4];
            double llddt = 1.0 - ce_m / c_m;
            double lmse  = (mse / g_mom[bb][1]) * (1.0 / 3.0);
            double tv = (double)t[bb];
            double wt = (tv * tv + 256.0) / ((tv + 16.0) * (tv + 16.0));
            loss += wt * (lmse + lbond) + llddt;
        }
        out[0] = (float)(loss / BATCH);
    }
}

// ---------------- launch ---------------------------------------------------
extern "C" void kernel_launch(void* const* d_in, const int* in_sizes, int n_in,
                              void* d_out, int out_size) {
    const float* x   = (const float*)d_in[0];
    const float* gt  = (const float*)d_in[1];
    const float* gm  = (const float*)d_in[2];
    const float* isp = (const float*)d_in[3];
    const float* isd = (const float*)d_in[4];
    const float* isr = (const float*)d_in[5];
    const float* isl = (const float*)d_in[6];
    const float* tb  = (const float*)d_in[7];
    const float* tm  = (const float*)d_in[8];
    const int*   npt = (const int*)d_in[9];
    const float* t   = (const float*)d_in[10];
    float* out = (float*)d_out;

    prep_kernel<<<BATCH, NTOK>>>(x, gt, gm, isp, isd, isr, isl, tm, npt, tb);
    sprep_kernel<<<dim3(NTOK, BATCH), NTOK>>>(isp, isd, isr, isl, tm, tb);
    pair_kernel<<<dim3(NPAIRS, BATCH), 256>>>();
    tail_kernel<<<1, 512>>>(t, out);
}